// round 14
// baseline (speedup 1.0000x reference)
#include <cuda_runtime.h>
#include <cuda_fp16.h>
#include <math.h>
#include <stdint.h>

#define BATCH   2
#define SEQL    2048
#define DEMB    2048
#define NHEADS  16
#define DHEAD   128
#define NTOK    (BATCH * SEQL)       // 4096
#define D3      (3 * DEMB)           // 6144

// combined score scale: log2(e)/sqrt(128), folded into Q at GEMM1 epilogue
#define QSC 0.1275174446f
#define NEGINF __int_as_float(0xff800000)

// -------- scratch (__device__ globals; no allocs allowed) --------
__device__ __half g_qkv [(size_t)NTOK * D3];     // 48 MB (fp16, Q pre-scaled)
__device__ __half g_attn[(size_t)NTOK * DEMB];   // 16 MB
__device__ __half g_xh  [(size_t)NTOK * DEMB];   // 16 MB (fp16 x)
__device__ __half g_wT1 [(size_t)D3   * DEMB];   // 24 MB (w_in^T fp16)
__device__ __half g_wT2 [(size_t)DEMB * DEMB];   //  8 MB (w_out^T fp16)

// ---------------- helpers ----------------
__device__ __forceinline__ uint32_t smem_u32(const void* p) {
    uint32_t a;
    asm("{ .reg .u64 t; cvta.to.shared.u64 t, %1; cvt.u32.u64 %0, t; }" : "=r"(a) : "l"(p));
    return a;
}
__device__ __forceinline__ float ex2(float x) {
    float y; asm("ex2.approx.f32 %0, %1;" : "=f"(y) : "f"(x)); return y;
}
__device__ __forceinline__ void cp_async16(uint32_t dst, const void* src) {
    asm volatile("cp.async.cg.shared.global [%0], [%1], 16;" :: "r"(dst), "l"(src) : "memory");
}
#define CP_COMMIT() asm volatile("cp.async.commit_group;" ::: "memory")
#define CP_WAIT(n)  asm volatile("cp.async.wait_group %0;" :: "n"(n) : "memory")

__device__ __forceinline__ void mma_f16(float* c, const uint32_t* a, const uint32_t* b) {
    asm volatile(
        "mma.sync.aligned.m16n8k16.row.col.f32.f16.f16.f32 "
        "{%0,%1,%2,%3}, {%4,%5,%6,%7}, {%8,%9}, {%0,%1,%2,%3};"
        : "+f"(c[0]), "+f"(c[1]), "+f"(c[2]), "+f"(c[3])
        : "r"(a[0]), "r"(a[1]), "r"(a[2]), "r"(a[3]), "r"(b[0]), "r"(b[1]));
}
__device__ __forceinline__ void ldsm_x4(uint32_t* r, uint32_t addr) {
    asm volatile("ldmatrix.sync.aligned.m8n8.x4.shared.b16 {%0,%1,%2,%3}, [%4];"
        : "=r"(r[0]), "=r"(r[1]), "=r"(r[2]), "=r"(r[3]) : "r"(addr));
}
__device__ __forceinline__ void ldsm_x4_trans(uint32_t* r, uint32_t addr) {
    asm volatile("ldmatrix.sync.aligned.m8n8.x4.trans.shared.b16 {%0,%1,%2,%3}, [%4];"
        : "=r"(r[0]), "=r"(r[1]), "=r"(r[2]), "=r"(r[3]) : "r"(addr));
}
__device__ __forceinline__ uint32_t packh2(float lo, float hi) {
    __half2 h = __floats2half2_rn(lo, hi);
    return *(uint32_t*)&h;
}

// ================================================================
// Prep kernels: fp16-convert x, transpose+convert weights to [N][K]
// ================================================================
__global__ void transpose_h_kernel(const float* __restrict__ src, __half* __restrict__ dst,
                                   int R, int C) {
    __shared__ float tile[32][33];
    int bx = blockIdx.x * 32, by = blockIdx.y * 32;
    int x = bx + threadIdx.x;
    for (int i = threadIdx.y; i < 32; i += 8)
        tile[i][threadIdx.x] = src[(size_t)(by + i) * C + x];
    __syncthreads();
    int ox = by + threadIdx.x;
    for (int i = threadIdx.y; i < 32; i += 8)
        dst[(size_t)(bx + i) * R + ox] = __float2half_rn(tile[threadIdx.x][i]);
}

__global__ void conv_h_kernel(const float* __restrict__ src, __half* __restrict__ dst, int n4) {
    int i = blockIdx.x * blockDim.x + threadIdx.x;
    if (i < n4) {
        float4 v = ((const float4*)src)[i];
        ((__half2*)dst)[2 * i]     = __floats2half2_rn(v.x, v.y);
        ((__half2*)dst)[2 * i + 1] = __floats2half2_rn(v.z, v.w);
    }
}

// ================================================================
// fp16 mma GEMM: C[M,N] = A[M,K] @ Bt[N,K]^T + bias[N]
// CTA 256x128, 512 threads, 16 warps (warp tile 64x32), K-chunk 64,
// 3-stage cp.async, paired-B ldmatrix, 1 CTA/SM.
// M%256==0, N%128==0, K%64==0.
// ================================================================
#define LDT 72
#define STG_H (384 * LDT)                                // A 256 rows + B 128 rows
#define STG_B (STG_H * 2)                                // 55296 B
#define GEMM_SMEM (3 * STG_B)                            // 165888 B

__global__ __launch_bounds__(512, 1) void f16_mma_gemm_kernel(
    const __half* __restrict__ A, const __half* __restrict__ Bt,
    const float* __restrict__ bias, __half* __restrict__ Ch, float* __restrict__ Cf,
    int M, int N, int K, int qcols)
{
    extern __shared__ __half smh[];
    const int tid  = threadIdx.x;
    const int lane = tid & 31;
    const int wid  = tid >> 5;
    const int wm = wid >> 2;           // 0..3  -> 64-row slab (256 rows)
    const int wn = wid & 3;            // 0..3  -> 32-col slab (128 cols)
    const int g = lane >> 2, t = lane & 3;
    const int bm = blockIdx.x * 256;
    const int bn = blockIdx.y * 128;
    const int nchunks = K >> 6;        // K / 64

    const int a_row  = (lane & 7) + ((lane >> 3) & 1) * 8;
    const int a_koff = (lane >> 4) * 8;
    const int pb_row  = (lane & 7) + ((lane >> 4) & 1) * 8;
    const int pb_koff = ((lane >> 3) & 1) * 8;

    const uint32_t smb = smem_u32(smh);

    float acc[4][4][4];
    #pragma unroll
    for (int mi = 0; mi < 4; mi++)
        #pragma unroll
        for (int ni = 0; ni < 4; ni++)
            #pragma unroll
            for (int q = 0; q < 4; q++) acc[mi][ni][q] = 0.0f;

    const int l_r  = tid >> 3;              // 0..63
    const int l_c8 = (tid & 7) * 8;

    auto load_stage = [&](int c, uint32_t baseA) {
        const int kb = c << 6;
        const uint32_t baseB = baseA + 256u * LDT * 2u;
        #pragma unroll
        for (int i = 0; i < 6; i++) {
            int r = l_r + i * 64;           // 0..383
            if (r < 256)
                cp_async16(baseA + (uint32_t)(r * LDT + l_c8) * 2u,
                           A + (size_t)(bm + r) * K + kb + l_c8);
            else
                cp_async16(baseB + (uint32_t)((r - 256) * LDT + l_c8) * 2u,
                           Bt + (size_t)(bn + r - 256) * K + kb + l_c8);
        }
        CP_COMMIT();
    };

    uint32_t sb0 = smb, sb1 = smb + STG_B, sb2 = smb + 2u * STG_B;

    load_stage(0, sb0);
    if (nchunks > 1) load_stage(1, sb1);

    for (int c = 0; c < nchunks; c++) {
        if (c + 1 < nchunks) { CP_WAIT(1); } else { CP_WAIT(0); }
        __syncthreads();

        if (c + 2 < nchunks) load_stage(c + 2, sb2);

        const uint32_t sAu = sb0;
        const uint32_t sBu = sb0 + 256u * LDT * 2u;
        #pragma unroll
        for (int ks = 0; ks < 4; ks++) {
            const int kb = ks * 16;
            uint32_t af[4][4], bf[2][4];
            #pragma unroll
            for (int mi = 0; mi < 4; mi++)
                ldsm_x4(af[mi],
                    sAu + (uint32_t)(((wm * 64 + mi * 16 + a_row) * LDT) + kb + a_koff) * 2u);
            #pragma unroll
            for (int nj = 0; nj < 2; nj++)
                ldsm_x4(bf[nj],
                    sBu + (uint32_t)(((wn * 32 + nj * 16 + pb_row) * LDT) + kb + pb_koff) * 2u);
            #pragma unroll
            for (int mi = 0; mi < 4; mi++)
                #pragma unroll
                for (int ni = 0; ni < 4; ni++)
                    mma_f16(acc[mi][ni], af[mi], bf[ni >> 1] + (ni & 1) * 2);
        }
        uint32_t tmp = sb0; sb0 = sb1; sb1 = sb2; sb2 = tmp;
    }
    __syncthreads();

    #pragma unroll
    for (int mi = 0; mi < 4; mi++) {
        const int r0 = bm + wm * 64 + mi * 16 + g;
        #pragma unroll
        for (int ni = 0; ni < 4; ni++) {
            const int n = bn + wn * 32 + ni * 8 + t * 2;
            const float sc = (n < qcols) ? QSC : 1.0f;
            float2 bv = *(const float2*)(bias + n);
            float v0 = (acc[mi][ni][0] + bv.x) * sc;
            float v1 = (acc[mi][ni][1] + bv.y) * sc;
            float v2 = (acc[mi][ni][2] + bv.x) * sc;
            float v3 = (acc[mi][ni][3] + bv.y) * sc;
            if (Ch) {
                *(__half2*)(Ch + (size_t)r0 * N + n)       = __floats2half2_rn(v0, v1);
                *(__half2*)(Ch + (size_t)(r0 + 8) * N + n) = __floats2half2_rn(v2, v3);
            } else {
                *(float2*)(Cf + (size_t)r0 * N + n)       = make_float2(v0, v1);
                *(float2*)(Cf + (size_t)(r0 + 8) * N + n) = make_float2(v2, v3);
            }
        }
    }
}

// ================================================================
// Flash attention, FA2-style (R10/R13 version — measured 142us):
// warp owns 16 q-rows x full kv/dh; warp-local softmax; reg-resident P;
// double-buffered K/V. 1 CTA/SM; smem = 5 tiles = 174080 B.
// ================================================================
#define LDH 136
#define FL_TILE (128 * LDH * 2)                         // 34816 B
#define FLB_Q   0
#define FLB_K0  (FL_TILE)
#define FLB_K1  (2 * FL_TILE)
#define FLB_V0  (3 * FL_TILE)
#define FLB_V1  (4 * FL_TILE)
#define FLASH_SMEM (5 * FL_TILE)                        // 174080 B

__global__ __launch_bounds__(256, 1) void flash_f16_kernel(
    const __half* __restrict__ qkv, __half* __restrict__ attn_out)
{
    extern __shared__ char smc[];

    const int qt  = (int)gridDim.x - 1 - (int)blockIdx.x;   // heavy first
    const int h   = blockIdx.y;
    const int b   = blockIdx.z;
    const int tid  = threadIdx.x;
    const int lane = tid & 31;
    const int wid  = tid >> 5;
    const int g = lane >> 2, t = lane & 3;

    const int a_row  = (lane & 7) + ((lane >> 3) & 1) * 8;
    const int a_koff = (lane >> 4) * 8;
    const int kb_row  = (lane & 7) + ((lane >> 4) & 1) * 8;
    const int kb_koff = ((lane >> 3) & 1) * 8;
    const int vb_row  = (lane & 7) + ((lane >> 3) & 1) * 8;
    const int vb_coff = ((lane >> 4) & 1) * 8;

    const uint32_t smb = smem_u32(smc);
    const uint32_t Qu  = smb + FLB_Q;
    const uint32_t Ku0 = smb + FLB_K0, Ku1 = smb + FLB_K1;
    const uint32_t Vu0 = smb + FLB_V0, Vu1 = smb + FLB_V1;

    const int l_r  = tid >> 4;               // 0..15
    const int l_c8 = (tid & 15) * 8;

    // ---- Q tile load (group 1) ----
    const __half* qbase = qkv + (size_t)(b * SEQL + qt * 128) * D3 + h * DHEAD;
    #pragma unroll
    for (int i = 0; i < 8; i++) {
        int r = l_r + i * 16;
        cp_async16(Qu + (uint32_t)(r * LDH + l_c8) * 2u, qbase + (size_t)r * D3 + l_c8);
    }
    CP_COMMIT();

    // ---- K0 / V0 loads (groups 2, 3) ----
    {
        const __half* kbase = qkv + (size_t)(b * SEQL) * D3 + DEMB + h * DHEAD;
        #pragma unroll
        for (int i = 0; i < 8; i++) {
            int r = l_r + i * 16;
            cp_async16(Ku0 + (uint32_t)(r * LDH + l_c8) * 2u, kbase + (size_t)r * D3 + l_c8);
        }
        CP_COMMIT();
        #pragma unroll
        for (int i = 0; i < 8; i++) {
            int r = l_r + i * 16;
            cp_async16(Vu0 + (uint32_t)(r * LDH + l_c8) * 2u,
                       kbase + DEMB + (size_t)r * D3 + l_c8);
        }
        CP_COMMIT();
    }

    float o[16][4];
    #pragma unroll
    for (int ni = 0; ni < 16; ni++)
        #pragma unroll
        for (int q = 0; q < 4; q++) o[ni][q] = 0.0f;
    float mrow0 = NEGINF, mrow1 = NEGINF, lrow0 = 0.0f, lrow1 = 0.0f;

    for (int jt = 0; jt <= qt; jt++) {
        const int p = jt & 1;
        const uint32_t Kcur = p ? Ku1 : Ku0;
        const uint32_t Vcur = p ? Vu1 : Vu0;

        // ---- prefetch next K/V into alternate buffers, then wait current ----
        if (jt < qt) {
            const uint32_t Knxt = p ? Ku0 : Ku1;
            const uint32_t Vnxt = p ? Vu0 : Vu1;
            const __half* kbn = qkv + (size_t)(b * SEQL + (jt + 1) * 128) * D3 + DEMB + h * DHEAD;
            #pragma unroll
            for (int i = 0; i < 8; i++) {
                int r = l_r + i * 16;
                cp_async16(Knxt + (uint32_t)(r * LDH + l_c8) * 2u, kbn + (size_t)r * D3 + l_c8);
            }
            CP_COMMIT();
            #pragma unroll
            for (int i = 0; i < 8; i++) {
                int r = l_r + i * 16;
                cp_async16(Vnxt + (uint32_t)(r * LDH + l_c8) * 2u,
                           kbn + DEMB + (size_t)r * D3 + l_c8);
            }
            CP_COMMIT();
            CP_WAIT(2);
        } else {
            CP_WAIT(0);
        }
        __syncthreads();

        // ---- S = Q @ K^T : warp computes 16 rows x 128 kv ----
        float s[16][4];
        #pragma unroll
        for (int ni = 0; ni < 16; ni++)
            #pragma unroll
            for (int q = 0; q < 4; q++) s[ni][q] = 0.0f;

        #pragma unroll
        for (int ks = 0; ks < 8; ks++) {
            const int kb = ks * 16;
            uint32_t af[4];
            ldsm_x4(af, Qu + (uint32_t)(((wid * 16 + a_row) * LDH) + kb + a_koff) * 2u);
            #pragma unroll
            for (int nj = 0; nj < 8; nj++) {
                uint32_t r4[4];
                ldsm_x4(r4, Kcur + (uint32_t)(((nj * 16 + kb_row) * LDH) + kb + kb_koff) * 2u);
                mma_f16(s[2 * nj],     af, r4);
                mma_f16(s[2 * nj + 1], af, r4 + 2);
            }
        }

        // ---- causal mask on diagonal tile ----
        if (jt == qt) {
            const int r0 = wid * 16 + g;
            #pragma unroll
            for (int ni = 0; ni < 16; ni++) {
                const int c = ni * 8 + 2 * t;
                if (c     > r0)     s[ni][0] = NEGINF;
                if (c + 1 > r0)     s[ni][1] = NEGINF;
                if (c     > r0 + 8) s[ni][2] = NEGINF;
                if (c + 1 > r0 + 8) s[ni][3] = NEGINF;
            }
        }

        // ---- row max (thread -> quad shfl; fully warp-local) ----
        float m0 = NEGINF, m1 = NEGINF;
        #pragma unroll
        for (int ni = 0; ni < 16; ni++) {
            m0 = fmaxf(m0, fmaxf(s[ni][0], s[ni][1]));
            m1 = fmaxf(m1, fmaxf(s[ni][2], s[ni][3]));
        }
        #pragma unroll
        for (int off = 1; off <= 2; off <<= 1) {
            m0 = fmaxf(m0, __shfl_xor_sync(0xffffffffu, m0, off));
            m1 = fmaxf(m1, __shfl_xor_sync(0xffffffffu, m1, off));
        }
        const float mn0 = fmaxf(mrow0, m0);
        const float mn1 = fmaxf(mrow1, m1);
        const float fsc0 = ex2(mrow0 - mn0);   // 0 on first tile
        const float fsc1 = ex2(mrow1 - mn1);
        mrow0 = mn0; mrow1 = mn1;

        // ---- exp + row sums ----
        float rs0 = 0.0f, rs1 = 0.0f;
        #pragma unroll
        for (int ni = 0; ni < 16; ni++) {
            s[ni][0] = ex2(s[ni][0] - mn0);
            s[ni][1] = ex2(s[ni][1] - mn0);
            s[ni][2] = ex2(s[ni][2] - mn1);
            s[ni][3] = ex2(s[ni][3] - mn1);
            rs0 += s[ni][0] + s[ni][1];
            rs1 += s[ni][2] + s[ni][3];
        }
        #pragma unroll
        for (int off = 1; off <= 2; off <<= 1) {
            rs0 += __shfl_xor_sync(0xffffffffu, rs0, off);
            rs1 += __shfl_xor_sync(0xffffffffu, rs1, off);
        }
        lrow0 = lrow0 * fsc0 + rs0;
        lrow1 = lrow1 * fsc1 + rs1;

        // ---- O rescale ----
        #pragma unroll
        for (int ni = 0; ni < 16; ni++) {
            o[ni][0] *= fsc0; o[ni][1] *= fsc0;
            o[ni][2] *= fsc1; o[ni][3] *= fsc1;
        }

        // ---- O += P @ V : P direct from registers ----
        #pragma unroll
        for (int ks = 0; ks < 8; ks++) {
            const int kb = ks * 16;
            uint32_t af[4];
            af[0] = packh2(s[2 * ks][0],     s[2 * ks][1]);
            af[1] = packh2(s[2 * ks][2],     s[2 * ks][3]);
            af[2] = packh2(s[2 * ks + 1][0], s[2 * ks + 1][1]);
            af[3] = packh2(s[2 * ks + 1][2], s[2 * ks + 1][3]);
            #pragma unroll
            for (int nj = 0; nj < 8; nj++) {
                uint32_t r4[4];
                ldsm_x4_trans(r4,
                    Vcur + (uint32_t)(((kb + vb_row) * LDH) + nj * 16 + vb_coff) * 2u);
                mma_f16(o[2 * nj],     af, r4);
                mma_f16(o[2 * nj + 1], af, r4 + 2);
            }
        }
        __syncthreads();       // buf p fully consumed before refill
    }

    // ---- epilogue: O /= l, fp16 out (feeds GEMM2) ----
    const size_t orow = (size_t)(b * SEQL + qt * 128) + wid * 16 + g;
    const float i0 = 1.0f / lrow0;
    const float i1 = 1.0f / lrow1;
    #pragma unroll
    for (int ni = 0; ni < 16; ni++) {
        const int cc = h * DHEAD + ni * 8 + 2 * t;
        *(__half2*)(attn_out + orow * DEMB + cc) =
            __floats2half2_rn(o[ni][0] * i0, o[ni][1] * i0);
        *(__half2*)(attn_out + (orow + 8) * DEMB + cc) =
            __floats2half2_rn(o[ni][2] * i1, o[ni][3] * i1);
    }
}

// ================================================================
// Launcher
// ================================================================
extern "C" void kernel_launch(void* const* d_in, const int* in_sizes, int n_in,
                              void* d_out, int out_size)
{
    (void)in_sizes; (void)n_in; (void)out_size;
    const float* x     = (const float*)d_in[0];
    const float* w_in  = (const float*)d_in[1];
    const float* b_in  = (const float*)d_in[2];
    const float* w_out = (const float*)d_in[3];
    const float* b_out = (const float*)d_in[4];
    float* out = (float*)d_out;

    void *qkv_p, *attn_p, *xh_p, *wT1_p, *wT2_p;
    cudaGetSymbolAddress(&qkv_p,  g_qkv);
    cudaGetSymbolAddress(&attn_p, g_attn);
    cudaGetSymbolAddress(&xh_p,   g_xh);
    cudaGetSymbolAddress(&wT1_p,  g_wT1);
    cudaGetSymbolAddress(&wT2_p,  g_wT2);

    cudaFuncSetAttribute(flash_f16_kernel,
                         cudaFuncAttributeMaxDynamicSharedMemorySize, FLASH_SMEM);
    cudaFuncSetAttribute(f16_mma_gemm_kernel,
                         cudaFuncAttributeMaxDynamicSharedMemorySize, GEMM_SMEM);

    // prep: wT1 = h(w_in^T), wT2 = h(w_out^T), xh = h(x)
    transpose_h_kernel<<<dim3(D3 / 32, DEMB / 32), dim3(32, 8)>>>(w_in, (__half*)wT1_p, DEMB, D3);
    transpose_h_kernel<<<dim3(DEMB / 32, DEMB / 32), dim3(32, 8)>>>(w_out, (__half*)wT2_p, DEMB, DEMB);
    conv_h_kernel<<<(NTOK * DEMB / 4 + 255) / 256, 256>>>(x, (__half*)xh_p, NTOK * DEMB / 4);

    // 1) qkv = x @ w_in + b_in  (fp16 out; Q cols pre-scaled by QSC)
    f16_mma_gemm_kernel<<<dim3(NTOK / 256, D3 / 128), 512, GEMM_SMEM>>>(
        (const __half*)xh_p, (const __half*)wT1_p, b_in,
        (__half*)qkv_p, nullptr, NTOK, D3, DEMB, DEMB);

    // 2) causal flash attention (R10 version) -> g_attn
    flash_f16_kernel<<<dim3(SEQL / 128, NHEADS, BATCH), 256, FLASH_SMEM>>>(
        (const __half*)qkv_p, (__half*)attn_p);

    // 3) out = attn @ w_out + b_out  (fp32 out)
    f16_mma_gemm_kernel<<<dim3(NTOK / 256, DEMB / 128), 512, GEMM_SMEM>>>(
        (const __half*)attn_p, (const __half*)wT2_p, b_out,
        nullptr, out, NTOK, DEMB, DEMB, 0);
}

// round 15
// speedup vs baseline: 1.1378x; 1.1378x over previous
#include <cuda_runtime.h>
#include <cuda_fp16.h>
#include <math.h>
#include <stdint.h>

#define BATCH   2
#define SEQL    2048
#define DEMB    2048
#define NHEADS  16
#define DHEAD   128
#define NTOK    (BATCH * SEQL)       // 4096
#define D3      (3 * DEMB)           // 6144
#define NQT     (SEQL / 128)         // 16 q-tiles

// combined score scale: log2(e)/sqrt(128), folded into Q at GEMM1 epilogue
#define QSC 0.1275174446f
#define NEGINF __int_as_float(0xff800000)

// -------- scratch (__device__ globals; no allocs allowed) --------
__device__ __half g_qkv [(size_t)NTOK * D3];     // 48 MB (fp16, Q pre-scaled)
__device__ __half g_attn[(size_t)NTOK * DEMB];   // 16 MB
__device__ __half g_xh  [(size_t)NTOK * DEMB];   // 16 MB (fp16 x)
__device__ __half g_wT1 [(size_t)D3   * DEMB];   // 24 MB (w_in^T fp16)
__device__ __half g_wT2 [(size_t)DEMB * DEMB];   //  8 MB (w_out^T fp16)

// ---------------- helpers ----------------
__device__ __forceinline__ uint32_t smem_u32(const void* p) {
    uint32_t a;
    asm("{ .reg .u64 t; cvta.to.shared.u64 t, %1; cvt.u32.u64 %0, t; }" : "=r"(a) : "l"(p));
    return a;
}
__device__ __forceinline__ float ex2(float x) {
    float y; asm("ex2.approx.f32 %0, %1;" : "=f"(y) : "f"(x)); return y;
}
__device__ __forceinline__ void cp_async16(uint32_t dst, const void* src) {
    asm volatile("cp.async.cg.shared.global [%0], [%1], 16;" :: "r"(dst), "l"(src) : "memory");
}
#define CP_COMMIT() asm volatile("cp.async.commit_group;" ::: "memory")
#define CP_WAIT(n)  asm volatile("cp.async.wait_group %0;" :: "n"(n) : "memory")

__device__ __forceinline__ void mma_f16(float* c, const uint32_t* a, const uint32_t* b) {
    asm volatile(
        "mma.sync.aligned.m16n8k16.row.col.f32.f16.f16.f32 "
        "{%0,%1,%2,%3}, {%4,%5,%6,%7}, {%8,%9}, {%0,%1,%2,%3};"
        : "+f"(c[0]), "+f"(c[1]), "+f"(c[2]), "+f"(c[3])
        : "r"(a[0]), "r"(a[1]), "r"(a[2]), "r"(a[3]), "r"(b[0]), "r"(b[1]));
}
__device__ __forceinline__ void ldsm_x4(uint32_t* r, uint32_t addr) {
    asm volatile("ldmatrix.sync.aligned.m8n8.x4.shared.b16 {%0,%1,%2,%3}, [%4];"
        : "=r"(r[0]), "=r"(r[1]), "=r"(r[2]), "=r"(r[3]) : "r"(addr));
}
__device__ __forceinline__ void ldsm_x4_trans(uint32_t* r, uint32_t addr) {
    asm volatile("ldmatrix.sync.aligned.m8n8.x4.trans.shared.b16 {%0,%1,%2,%3}, [%4];"
        : "=r"(r[0]), "=r"(r[1]), "=r"(r[2]), "=r"(r[3]) : "r"(addr));
}
__device__ __forceinline__ uint32_t packh2(float lo, float hi) {
    __half2 h = __floats2half2_rn(lo, hi);
    return *(uint32_t*)&h;
}

// ================================================================
// Prep kernels: fp16-convert x, transpose+convert weights to [N][K]
// ================================================================
__global__ void transpose_h_kernel(const float* __restrict__ src, __half* __restrict__ dst,
                                   int R, int C) {
    __shared__ float tile[32][33];
    int bx = blockIdx.x * 32, by = blockIdx.y * 32;
    int x = bx + threadIdx.x;
    for (int i = threadIdx.y; i < 32; i += 8)
        tile[i][threadIdx.x] = src[(size_t)(by + i) * C + x];
    __syncthreads();
    int ox = by + threadIdx.x;
    for (int i = threadIdx.y; i < 32; i += 8)
        dst[(size_t)(bx + i) * R + ox] = __float2half_rn(tile[threadIdx.x][i]);
}

__global__ void conv_h_kernel(const float* __restrict__ src, __half* __restrict__ dst, int n4) {
    int i = blockIdx.x * blockDim.x + threadIdx.x;
    if (i < n4) {
        float4 v = ((const float4*)src)[i];
        ((__half2*)dst)[2 * i]     = __floats2half2_rn(v.x, v.y);
        ((__half2*)dst)[2 * i + 1] = __floats2half2_rn(v.z, v.w);
    }
}

// ================================================================
// fp16 mma GEMM (R13 version): CTA 128x128, warp 64x32, K-chunk 64,
// 3-stage cp.async, paired-B ldmatrix, 2 CTAs/SM.
// ================================================================
#define LDT 72
#define STG_H (256 * LDT)
#define STG_B (STG_H * 2)
#define GEMM_SMEM (3 * STG_B)                            // 110592 B

__global__ __launch_bounds__(256, 2) void f16_mma_gemm_kernel(
    const __half* __restrict__ A, const __half* __restrict__ Bt,
    const float* __restrict__ bias, __half* __restrict__ Ch, float* __restrict__ Cf,
    int M, int N, int K, int qcols)
{
    extern __shared__ __half smh[];
    const int tid  = threadIdx.x;
    const int lane = tid & 31;
    const int wid  = tid >> 5;
    const int wm = wid >> 2;
    const int wn = wid & 3;
    const int g = lane >> 2, t = lane & 3;
    const int bm = blockIdx.x * 128;
    const int bn = blockIdx.y * 128;
    const int nchunks = K >> 6;

    const int a_row  = (lane & 7) + ((lane >> 3) & 1) * 8;
    const int a_koff = (lane >> 4) * 8;
    const int pb_row  = (lane & 7) + ((lane >> 4) & 1) * 8;
    const int pb_koff = ((lane >> 3) & 1) * 8;

    const uint32_t smb = smem_u32(smh);

    float acc[4][4][4];
    #pragma unroll
    for (int mi = 0; mi < 4; mi++)
        #pragma unroll
        for (int ni = 0; ni < 4; ni++)
            #pragma unroll
            for (int q = 0; q < 4; q++) acc[mi][ni][q] = 0.0f;

    const int l_r  = tid >> 3;
    const int l_c8 = (tid & 7) * 8;

    auto load_stage = [&](int c, uint32_t baseA) {
        const int kb = c << 6;
        const uint32_t baseB = baseA + 128u * LDT * 2u;
        #pragma unroll
        for (int i = 0; i < 8; i++) {
            int r = l_r + i * 32;
            if (r < 128)
                cp_async16(baseA + (uint32_t)(r * LDT + l_c8) * 2u,
                           A + (size_t)(bm + r) * K + kb + l_c8);
            else
                cp_async16(baseB + (uint32_t)((r - 128) * LDT + l_c8) * 2u,
                           Bt + (size_t)(bn + r - 128) * K + kb + l_c8);
        }
        CP_COMMIT();
    };

    uint32_t sb0 = smb, sb1 = smb + STG_B, sb2 = smb + 2u * STG_B;

    load_stage(0, sb0);
    if (nchunks > 1) load_stage(1, sb1);

    for (int c = 0; c < nchunks; c++) {
        if (c + 1 < nchunks) { CP_WAIT(1); } else { CP_WAIT(0); }
        __syncthreads();

        if (c + 2 < nchunks) load_stage(c + 2, sb2);

        const uint32_t sAu = sb0;
        const uint32_t sBu = sb0 + 128u * LDT * 2u;
        #pragma unroll
        for (int ks = 0; ks < 4; ks++) {
            const int kb = ks * 16;
            uint32_t af[4][4], bf[2][4];
            #pragma unroll
            for (int mi = 0; mi < 4; mi++)
                ldsm_x4(af[mi],
                    sAu + (uint32_t)(((wm * 64 + mi * 16 + a_row) * LDT) + kb + a_koff) * 2u);
            #pragma unroll
            for (int nj = 0; nj < 2; nj++)
                ldsm_x4(bf[nj],
                    sBu + (uint32_t)(((wn * 32 + nj * 16 + pb_row) * LDT) + kb + pb_koff) * 2u);
            #pragma unroll
            for (int mi = 0; mi < 4; mi++)
                #pragma unroll
                for (int ni = 0; ni < 4; ni++)
                    mma_f16(acc[mi][ni], af[mi], bf[ni >> 1] + (ni & 1) * 2);
        }
        uint32_t tmp = sb0; sb0 = sb1; sb1 = sb2; sb2 = tmp;
    }
    __syncthreads();

    #pragma unroll
    for (int mi = 0; mi < 4; mi++) {
        const int r0 = bm + wm * 64 + mi * 16 + g;
        #pragma unroll
        for (int ni = 0; ni < 4; ni++) {
            const int n = bn + wn * 32 + ni * 8 + t * 2;
            const float sc = (n < qcols) ? QSC : 1.0f;
            float2 bv = *(const float2*)(bias + n);
            float v0 = (acc[mi][ni][0] + bv.x) * sc;
            float v1 = (acc[mi][ni][1] + bv.y) * sc;
            float v2 = (acc[mi][ni][2] + bv.x) * sc;
            float v3 = (acc[mi][ni][3] + bv.y) * sc;
            if (Ch) {
                *(__half2*)(Ch + (size_t)r0 * N + n)       = __floats2half2_rn(v0, v1);
                *(__half2*)(Ch + (size_t)(r0 + 8) * N + n) = __floats2half2_rn(v2, v3);
            } else {
                *(float2*)(Cf + (size_t)r0 * N + n)       = make_float2(v0, v1);
                *(float2*)(Cf + (size_t)(r0 + 8) * N + n) = make_float2(v2, v3);
            }
        }
    }
}

// ================================================================
// Flash attention, FA2-style with CAUSAL WORK PAIRING:
// each CTA handles q-tiles (NQT-1-bx) then (bx): uniform 17 iters.
// Per-tile body identical to R13 (measured). 1 CTA/SM.
// ================================================================
#define LDH 136
#define FL_TILE (128 * LDH * 2)                         // 34816 B
#define FLB_Q   0
#define FLB_K0  (FL_TILE)
#define FLB_K1  (2 * FL_TILE)
#define FLB_V0  (3 * FL_TILE)
#define FLB_V1  (4 * FL_TILE)
#define FLASH_SMEM (5 * FL_TILE)                        // 174080 B

__global__ __launch_bounds__(256, 1) void flash_f16_kernel(
    const __half* __restrict__ qkv, __half* __restrict__ attn_out)
{
    extern __shared__ char smc[];

    const int h   = blockIdx.y;
    const int b   = blockIdx.z;
    const int tid  = threadIdx.x;
    const int lane = tid & 31;
    const int wid  = tid >> 5;
    const int g = lane >> 2, t = lane & 3;

    const int a_row  = (lane & 7) + ((lane >> 3) & 1) * 8;
    const int a_koff = (lane >> 4) * 8;
    const int kb_row  = (lane & 7) + ((lane >> 4) & 1) * 8;
    const int kb_koff = ((lane >> 3) & 1) * 8;
    const int vb_row  = (lane & 7) + ((lane >> 3) & 1) * 8;
    const int vb_coff = ((lane >> 4) & 1) * 8;

    const uint32_t smb = smem_u32(smc);
    const uint32_t Qu  = smb + FLB_Q;
    const uint32_t Ku0 = smb + FLB_K0, Ku1 = smb + FLB_K1;
    const uint32_t Vu0 = smb + FLB_V0, Vu1 = smb + FLB_V1;

    const int l_r  = tid >> 4;               // 0..15
    const int l_c8 = (tid & 15) * 8;

    #pragma unroll
    for (int half = 0; half < 2; half++) {
        // heavy tile first, then its light complement: work = 17 iters total
        const int qt = half == 0 ? (NQT - 1 - (int)blockIdx.x) : (int)blockIdx.x;

        // ---- Q tile load (group) ----
        const __half* qbase = qkv + (size_t)(b * SEQL + qt * 128) * D3 + h * DHEAD;
        #pragma unroll
        for (int i = 0; i < 8; i++) {
            int r = l_r + i * 16;
            cp_async16(Qu + (uint32_t)(r * LDH + l_c8) * 2u, qbase + (size_t)r * D3 + l_c8);
        }
        CP_COMMIT();

        // ---- K0 / V0 loads (groups) ----
        {
            const __half* kbase = qkv + (size_t)(b * SEQL) * D3 + DEMB + h * DHEAD;
            #pragma unroll
            for (int i = 0; i < 8; i++) {
                int r = l_r + i * 16;
                cp_async16(Ku0 + (uint32_t)(r * LDH + l_c8) * 2u, kbase + (size_t)r * D3 + l_c8);
            }
            CP_COMMIT();
            #pragma unroll
            for (int i = 0; i < 8; i++) {
                int r = l_r + i * 16;
                cp_async16(Vu0 + (uint32_t)(r * LDH + l_c8) * 2u,
                           kbase + DEMB + (size_t)r * D3 + l_c8);
            }
            CP_COMMIT();
        }

        float o[16][4];
        #pragma unroll
        for (int ni = 0; ni < 16; ni++)
            #pragma unroll
            for (int q = 0; q < 4; q++) o[ni][q] = 0.0f;
        float mrow0 = NEGINF, mrow1 = NEGINF, lrow0 = 0.0f, lrow1 = 0.0f;

        for (int jt = 0; jt <= qt; jt++) {
            const int p = jt & 1;
            const uint32_t Kcur = p ? Ku1 : Ku0;
            const uint32_t Vcur = p ? Vu1 : Vu0;

            // ---- prefetch next K/V, then wait current ----
            if (jt < qt) {
                const uint32_t Knxt = p ? Ku0 : Ku1;
                const uint32_t Vnxt = p ? Vu0 : Vu1;
                const __half* kbn = qkv + (size_t)(b * SEQL + (jt + 1) * 128) * D3 + DEMB + h * DHEAD;
                #pragma unroll
                for (int i = 0; i < 8; i++) {
                    int r = l_r + i * 16;
                    cp_async16(Knxt + (uint32_t)(r * LDH + l_c8) * 2u, kbn + (size_t)r * D3 + l_c8);
                }
                CP_COMMIT();
                #pragma unroll
                for (int i = 0; i < 8; i++) {
                    int r = l_r + i * 16;
                    cp_async16(Vnxt + (uint32_t)(r * LDH + l_c8) * 2u,
                               kbn + DEMB + (size_t)r * D3 + l_c8);
                }
                CP_COMMIT();
                CP_WAIT(2);
            } else {
                CP_WAIT(0);
            }
            __syncthreads();

            // ---- S = Q @ K^T ----
            float s[16][4];
            #pragma unroll
            for (int ni = 0; ni < 16; ni++)
                #pragma unroll
                for (int q = 0; q < 4; q++) s[ni][q] = 0.0f;

            #pragma unroll
            for (int ks = 0; ks < 8; ks++) {
                const int kb = ks * 16;
                uint32_t af[4];
                ldsm_x4(af, Qu + (uint32_t)(((wid * 16 + a_row) * LDH) + kb + a_koff) * 2u);
                #pragma unroll
                for (int nj = 0; nj < 8; nj++) {
                    uint32_t r4[4];
                    ldsm_x4(r4, Kcur + (uint32_t)(((nj * 16 + kb_row) * LDH) + kb + kb_koff) * 2u);
                    mma_f16(s[2 * nj],     af, r4);
                    mma_f16(s[2 * nj + 1], af, r4 + 2);
                }
            }

            // ---- causal mask on diagonal tile ----
            if (jt == qt) {
                const int r0 = wid * 16 + g;
                #pragma unroll
                for (int ni = 0; ni < 16; ni++) {
                    const int c = ni * 8 + 2 * t;
                    if (c     > r0)     s[ni][0] = NEGINF;
                    if (c + 1 > r0)     s[ni][1] = NEGINF;
                    if (c     > r0 + 8) s[ni][2] = NEGINF;
                    if (c + 1 > r0 + 8) s[ni][3] = NEGINF;
                }
            }

            // ---- row max (warp-local) ----
            float m0 = NEGINF, m1 = NEGINF;
            #pragma unroll
            for (int ni = 0; ni < 16; ni++) {
                m0 = fmaxf(m0, fmaxf(s[ni][0], s[ni][1]));
                m1 = fmaxf(m1, fmaxf(s[ni][2], s[ni][3]));
            }
            #pragma unroll
            for (int off = 1; off <= 2; off <<= 1) {
                m0 = fmaxf(m0, __shfl_xor_sync(0xffffffffu, m0, off));
                m1 = fmaxf(m1, __shfl_xor_sync(0xffffffffu, m1, off));
            }
            const float mn0 = fmaxf(mrow0, m0);
            const float mn1 = fmaxf(mrow1, m1);
            const float fsc0 = ex2(mrow0 - mn0);
            const float fsc1 = ex2(mrow1 - mn1);
            mrow0 = mn0; mrow1 = mn1;

            // ---- exp + row sums ----
            float rs0 = 0.0f, rs1 = 0.0f;
            #pragma unroll
            for (int ni = 0; ni < 16; ni++) {
                s[ni][0] = ex2(s[ni][0] - mn0);
                s[ni][1] = ex2(s[ni][1] - mn0);
                s[ni][2] = ex2(s[ni][2] - mn1);
                s[ni][3] = ex2(s[ni][3] - mn1);
                rs0 += s[ni][0] + s[ni][1];
                rs1 += s[ni][2] + s[ni][3];
            }
            #pragma unroll
            for (int off = 1; off <= 2; off <<= 1) {
                rs0 += __shfl_xor_sync(0xffffffffu, rs0, off);
                rs1 += __shfl_xor_sync(0xffffffffu, rs1, off);
            }
            lrow0 = lrow0 * fsc0 + rs0;
            lrow1 = lrow1 * fsc1 + rs1;

            // ---- O rescale ----
            #pragma unroll
            for (int ni = 0; ni < 16; ni++) {
                o[ni][0] *= fsc0; o[ni][1] *= fsc0;
                o[ni][2] *= fsc1; o[ni][3] *= fsc1;
            }

            // ---- O += P @ V : P direct from registers ----
            #pragma unroll
            for (int ks = 0; ks < 8; ks++) {
                const int kb = ks * 16;
                uint32_t af[4];
                af[0] = packh2(s[2 * ks][0],     s[2 * ks][1]);
                af[1] = packh2(s[2 * ks][2],     s[2 * ks][3]);
                af[2] = packh2(s[2 * ks + 1][0], s[2 * ks + 1][1]);
                af[3] = packh2(s[2 * ks + 1][2], s[2 * ks + 1][3]);
                #pragma unroll
                for (int nj = 0; nj < 8; nj++) {
                    uint32_t r4[4];
                    ldsm_x4_trans(r4,
                        Vcur + (uint32_t)(((kb + vb_row) * LDH) + nj * 16 + vb_coff) * 2u);
                    mma_f16(o[2 * nj],     af, r4);
                    mma_f16(o[2 * nj + 1], af, r4 + 2);
                }
            }
            __syncthreads();       // buffers fully consumed before refill
        }

        // ---- epilogue: O /= l, fp16 out ----
        const size_t orow = (size_t)(b * SEQL + qt * 128) + wid * 16 + g;
        const float i0 = 1.0f / lrow0;
        const float i1 = 1.0f / lrow1;
        #pragma unroll
        for (int ni = 0; ni < 16; ni++) {
            const int cc = h * DHEAD + ni * 8 + 2 * t;
            *(__half2*)(attn_out + orow * DEMB + cc) =
                __floats2half2_rn(o[ni][0] * i0, o[ni][1] * i0);
            *(__half2*)(attn_out + (orow + 8) * DEMB + cc) =
                __floats2half2_rn(o[ni][2] * i1, o[ni][3] * i1);
        }
        __syncthreads();           // epilogue done before next tile's loads
    }
}

// ================================================================
// Launcher
// ================================================================
extern "C" void kernel_launch(void* const* d_in, const int* in_sizes, int n_in,
                              void* d_out, int out_size)
{
    (void)in_sizes; (void)n_in; (void)out_size;
    const float* x     = (const float*)d_in[0];
    const float* w_in  = (const float*)d_in[1];
    const float* b_in  = (const float*)d_in[2];
    const float* w_out = (const float*)d_in[3];
    const float* b_out = (const float*)d_in[4];
    float* out = (float*)d_out;

    void *qkv_p, *attn_p, *xh_p, *wT1_p, *wT2_p;
    cudaGetSymbolAddress(&qkv_p,  g_qkv);
    cudaGetSymbolAddress(&attn_p, g_attn);
    cudaGetSymbolAddress(&xh_p,   g_xh);
    cudaGetSymbolAddress(&wT1_p,  g_wT1);
    cudaGetSymbolAddress(&wT2_p,  g_wT2);

    cudaFuncSetAttribute(flash_f16_kernel,
                         cudaFuncAttributeMaxDynamicSharedMemorySize, FLASH_SMEM);
    cudaFuncSetAttribute(f16_mma_gemm_kernel,
                         cudaFuncAttributeMaxDynamicSharedMemorySize, GEMM_SMEM);

    // prep: wT1 = h(w_in^T), wT2 = h(w_out^T), xh = h(x)
    transpose_h_kernel<<<dim3(D3 / 32, DEMB / 32), dim3(32, 8)>>>(w_in, (__half*)wT1_p, DEMB, D3);
    transpose_h_kernel<<<dim3(DEMB / 32, DEMB / 32), dim3(32, 8)>>>(w_out, (__half*)wT2_p, DEMB, DEMB);
    conv_h_kernel<<<(NTOK * DEMB / 4 + 255) / 256, 256>>>(x, (__half*)xh_p, NTOK * DEMB / 4);

    // 1) qkv = x @ w_in + b_in  (fp16 out; Q cols pre-scaled by QSC)
    f16_mma_gemm_kernel<<<dim3(NTOK / 128, D3 / 128), 256, GEMM_SMEM>>>(
        (const __half*)xh_p, (const __half*)wT1_p, b_in,
        (__half*)qkv_p, nullptr, NTOK, D3, DEMB, DEMB);

    // 2) causal flash attention (paired q-tiles: uniform work) -> g_attn
    flash_f16_kernel<<<dim3(NQT / 2, NHEADS, BATCH), 256, FLASH_SMEM>>>(
        (const __half*)qkv_p, (__half*)attn_p);

    // 3) out = attn @ w_out + b_out  (fp32 out)
    f16_mma_gemm_kernel<<<dim3(NTOK / 128, DEMB / 128), 256, GEMM_SMEM>>>(
        (const __half*)attn_p, (const __half*)wT2_p, b_out,
        nullptr, out, NTOK, DEMB, DEMB, 0);
}

// round 16
// speedup vs baseline: 1.1381x; 1.0003x over previous
#include <cuda_runtime.h>
#include <cuda_fp16.h>
#include <math.h>
#include <stdint.h>

#define BATCH   2
#define SEQL    2048
#define DEMB    2048
#define NHEADS  16
#define DHEAD   128
#define NTOK    (BATCH * SEQL)       // 4096
#define D3      (3 * DEMB)           // 6144
#define NQT     (SEQL / 128)         // 16 q-tiles

// combined score scale: log2(e)/sqrt(128), folded into Q at GEMM1 epilogue
#define QSC 0.1275174446f
#define NEGINF __int_as_float(0xff800000)

// -------- scratch (__device__ globals; no allocs allowed) --------
__device__ __half g_qkv [(size_t)NTOK * D3];     // 48 MB (fp16, Q pre-scaled)
__device__ __half g_attn[(size_t)NTOK * DEMB];   // 16 MB
__device__ __half g_xh  [(size_t)NTOK * DEMB];   // 16 MB (fp16 x)
__device__ __half g_wT1 [(size_t)D3   * DEMB];   // 24 MB (w_in^T fp16)
__device__ __half g_wT2 [(size_t)DEMB * DEMB];   //  8 MB (w_out^T fp16)

// ---------------- helpers ----------------
__device__ __forceinline__ uint32_t smem_u32(const void* p) {
    uint32_t a;
    asm("{ .reg .u64 t; cvta.to.shared.u64 t, %1; cvt.u32.u64 %0, t; }" : "=r"(a) : "l"(p));
    return a;
}
__device__ __forceinline__ float ex2(float x) {
    float y; asm("ex2.approx.f32 %0, %1;" : "=f"(y) : "f"(x)); return y;
}
__device__ __forceinline__ void cp_async16(uint32_t dst, const void* src) {
    asm volatile("cp.async.cg.shared.global [%0], [%1], 16;" :: "r"(dst), "l"(src) : "memory");
}
#define CP_COMMIT() asm volatile("cp.async.commit_group;" ::: "memory")
#define CP_WAIT(n)  asm volatile("cp.async.wait_group %0;" :: "n"(n) : "memory")

__device__ __forceinline__ void mma_f16(float* c, const uint32_t* a, const uint32_t* b) {
    asm volatile(
        "mma.sync.aligned.m16n8k16.row.col.f32.f16.f16.f32 "
        "{%0,%1,%2,%3}, {%4,%5,%6,%7}, {%8,%9}, {%0,%1,%2,%3};"
        : "+f"(c[0]), "+f"(c[1]), "+f"(c[2]), "+f"(c[3])
        : "r"(a[0]), "r"(a[1]), "r"(a[2]), "r"(a[3]), "r"(b[0]), "r"(b[1]));
}
__device__ __forceinline__ void ldsm_x4(uint32_t* r, uint32_t addr) {
    asm volatile("ldmatrix.sync.aligned.m8n8.x4.shared.b16 {%0,%1,%2,%3}, [%4];"
        : "=r"(r[0]), "=r"(r[1]), "=r"(r[2]), "=r"(r[3]) : "r"(addr));
}
__device__ __forceinline__ void ldsm_x4_trans(uint32_t* r, uint32_t addr) {
    asm volatile("ldmatrix.sync.aligned.m8n8.x4.trans.shared.b16 {%0,%1,%2,%3}, [%4];"
        : "=r"(r[0]), "=r"(r[1]), "=r"(r[2]), "=r"(r[3]) : "r"(addr));
}
__device__ __forceinline__ uint32_t packh2(float lo, float hi) {
    __half2 h = __floats2half2_rn(lo, hi);
    return *(uint32_t*)&h;
}

// ================================================================
// Prep kernels: fp16-convert x, transpose+convert weights to [N][K]
// ================================================================
__global__ void transpose_h_kernel(const float* __restrict__ src, __half* __restrict__ dst,
                                   int R, int C) {
    __shared__ float tile[32][33];
    int bx = blockIdx.x * 32, by = blockIdx.y * 32;
    int x = bx + threadIdx.x;
    for (int i = threadIdx.y; i < 32; i += 8)
        tile[i][threadIdx.x] = src[(size_t)(by + i) * C + x];
    __syncthreads();
    int ox = by + threadIdx.x;
    for (int i = threadIdx.y; i < 32; i += 8)
        dst[(size_t)(bx + i) * R + ox] = __float2half_rn(tile[threadIdx.x][i]);
}

__global__ void conv_h_kernel(const float* __restrict__ src, __half* __restrict__ dst, int n4) {
    int i = blockIdx.x * blockDim.x + threadIdx.x;
    if (i < n4) {
        float4 v = ((const float4*)src)[i];
        ((__half2*)dst)[2 * i]     = __floats2half2_rn(v.x, v.y);
        ((__half2*)dst)[2 * i + 1] = __floats2half2_rn(v.z, v.w);
    }
}

// ================================================================
// fp16 mma GEMM (R13 version): CTA 128x128, warp 64x32, K-chunk 64,
// 3-stage cp.async, paired-B ldmatrix, 2 CTAs/SM.
// ================================================================
#define LDT 72
#define STG_H (256 * LDT)
#define STG_B (STG_H * 2)
#define GEMM_SMEM (3 * STG_B)                            // 110592 B

__global__ __launch_bounds__(256, 2) void f16_mma_gemm_kernel(
    const __half* __restrict__ A, const __half* __restrict__ Bt,
    const float* __restrict__ bias, __half* __restrict__ Ch, float* __restrict__ Cf,
    int M, int N, int K, int qcols)
{
    extern __shared__ __half smh[];
    const int tid  = threadIdx.x;
    const int lane = tid & 31;
    const int wid  = tid >> 5;
    const int wm = wid >> 2;
    const int wn = wid & 3;
    const int g = lane >> 2, t = lane & 3;
    const int bm = blockIdx.x * 128;
    const int bn = blockIdx.y * 128;
    const int nchunks = K >> 6;

    const int a_row  = (lane & 7) + ((lane >> 3) & 1) * 8;
    const int a_koff = (lane >> 4) * 8;
    const int pb_row  = (lane & 7) + ((lane >> 4) & 1) * 8;
    const int pb_koff = ((lane >> 3) & 1) * 8;

    const uint32_t smb = smem_u32(smh);

    float acc[4][4][4];
    #pragma unroll
    for (int mi = 0; mi < 4; mi++)
        #pragma unroll
        for (int ni = 0; ni < 4; ni++)
            #pragma unroll
            for (int q = 0; q < 4; q++) acc[mi][ni][q] = 0.0f;

    const int l_r  = tid >> 3;
    const int l_c8 = (tid & 7) * 8;

    auto load_stage = [&](int c, uint32_t baseA) {
        const int kb = c << 6;
        const uint32_t baseB = baseA + 128u * LDT * 2u;
        #pragma unroll
        for (int i = 0; i < 8; i++) {
            int r = l_r + i * 32;
            if (r < 128)
                cp_async16(baseA + (uint32_t)(r * LDT + l_c8) * 2u,
                           A + (size_t)(bm + r) * K + kb + l_c8);
            else
                cp_async16(baseB + (uint32_t)((r - 128) * LDT + l_c8) * 2u,
                           Bt + (size_t)(bn + r - 128) * K + kb + l_c8);
        }
        CP_COMMIT();
    };

    uint32_t sb0 = smb, sb1 = smb + STG_B, sb2 = smb + 2u * STG_B;

    load_stage(0, sb0);
    if (nchunks > 1) load_stage(1, sb1);

    for (int c = 0; c < nchunks; c++) {
        if (c + 1 < nchunks) { CP_WAIT(1); } else { CP_WAIT(0); }
        __syncthreads();

        if (c + 2 < nchunks) load_stage(c + 2, sb2);

        const uint32_t sAu = sb0;
        const uint32_t sBu = sb0 + 128u * LDT * 2u;
        #pragma unroll
        for (int ks = 0; ks < 4; ks++) {
            const int kb = ks * 16;
            uint32_t af[4][4], bf[2][4];
            #pragma unroll
            for (int mi = 0; mi < 4; mi++)
                ldsm_x4(af[mi],
                    sAu + (uint32_t)(((wm * 64 + mi * 16 + a_row) * LDT) + kb + a_koff) * 2u);
            #pragma unroll
            for (int nj = 0; nj < 2; nj++)
                ldsm_x4(bf[nj],
                    sBu + (uint32_t)(((wn * 32 + nj * 16 + pb_row) * LDT) + kb + pb_koff) * 2u);
            #pragma unroll
            for (int mi = 0; mi < 4; mi++)
                #pragma unroll
                for (int ni = 0; ni < 4; ni++)
                    mma_f16(acc[mi][ni], af[mi], bf[ni >> 1] + (ni & 1) * 2);
        }
        uint32_t tmp = sb0; sb0 = sb1; sb1 = sb2; sb2 = tmp;
    }
    __syncthreads();

    #pragma unroll
    for (int mi = 0; mi < 4; mi++) {
        const int r0 = bm + wm * 64 + mi * 16 + g;
        #pragma unroll
        for (int ni = 0; ni < 4; ni++) {
            const int n = bn + wn * 32 + ni * 8 + t * 2;
            const float sc = (n < qcols) ? QSC : 1.0f;
            float2 bv = *(const float2*)(bias + n);
            float v0 = (acc[mi][ni][0] + bv.x) * sc;
            float v1 = (acc[mi][ni][1] + bv.y) * sc;
            float v2 = (acc[mi][ni][2] + bv.x) * sc;
            float v3 = (acc[mi][ni][3] + bv.y) * sc;
            if (Ch) {
                *(__half2*)(Ch + (size_t)r0 * N + n)       = __floats2half2_rn(v0, v1);
                *(__half2*)(Ch + (size_t)(r0 + 8) * N + n) = __floats2half2_rn(v2, v3);
            } else {
                *(float2*)(Cf + (size_t)r0 * N + n)       = make_float2(v0, v1);
                *(float2*)(Cf + (size_t)(r0 + 8) * N + n) = make_float2(v2, v3);
            }
        }
    }
}

// ================================================================
// Flash attention, FA2-style, paired q-tiles, SINGLE barrier per
// iteration: CP_WAIT(0); barrier; [prefetch jt+1]; compute.
// Reads of old buffers all precede the barrier; prefetch overwrites
// after it — one barrier orders both visibility and reuse.
// ================================================================
#define LDH 136
#define FL_TILE (128 * LDH * 2)                         // 34816 B
#define FLB_Q   0
#define FLB_K0  (FL_TILE)
#define FLB_K1  (2 * FL_TILE)
#define FLB_V0  (3 * FL_TILE)
#define FLB_V1  (4 * FL_TILE)
#define FLASH_SMEM (5 * FL_TILE)                        // 174080 B

__global__ __launch_bounds__(256, 1) void flash_f16_kernel(
    const __half* __restrict__ qkv, __half* __restrict__ attn_out)
{
    extern __shared__ char smc[];

    const int h   = blockIdx.y;
    const int b   = blockIdx.z;
    const int tid  = threadIdx.x;
    const int lane = tid & 31;
    const int wid  = tid >> 5;
    const int g = lane >> 2, t = lane & 3;

    const int a_row  = (lane & 7) + ((lane >> 3) & 1) * 8;
    const int a_koff = (lane >> 4) * 8;
    const int kb_row  = (lane & 7) + ((lane >> 4) & 1) * 8;
    const int kb_koff = ((lane >> 3) & 1) * 8;
    const int vb_row  = (lane & 7) + ((lane >> 3) & 1) * 8;
    const int vb_coff = ((lane >> 4) & 1) * 8;

    const uint32_t smb = smem_u32(smc);
    const uint32_t Qu  = smb + FLB_Q;
    const uint32_t Ku0 = smb + FLB_K0, Ku1 = smb + FLB_K1;
    const uint32_t Vu0 = smb + FLB_V0, Vu1 = smb + FLB_V1;

    const int l_r  = tid >> 4;               // 0..15
    const int l_c8 = (tid & 15) * 8;

    #pragma unroll
    for (int half = 0; half < 2; half++) {
        // heavy tile first, then its light complement: uniform 17 iters/CTA
        const int qt = half == 0 ? (NQT - 1 - (int)blockIdx.x) : (int)blockIdx.x;

        // ---- Q, K0, V0 loads (3 groups) ----
        const __half* qbase = qkv + (size_t)(b * SEQL + qt * 128) * D3 + h * DHEAD;
        #pragma unroll
        for (int i = 0; i < 8; i++) {
            int r = l_r + i * 16;
            cp_async16(Qu + (uint32_t)(r * LDH + l_c8) * 2u, qbase + (size_t)r * D3 + l_c8);
        }
        CP_COMMIT();
        {
            const __half* kbase = qkv + (size_t)(b * SEQL) * D3 + DEMB + h * DHEAD;
            #pragma unroll
            for (int i = 0; i < 8; i++) {
                int r = l_r + i * 16;
                cp_async16(Ku0 + (uint32_t)(r * LDH + l_c8) * 2u, kbase + (size_t)r * D3 + l_c8);
            }
            CP_COMMIT();
            #pragma unroll
            for (int i = 0; i < 8; i++) {
                int r = l_r + i * 16;
                cp_async16(Vu0 + (uint32_t)(r * LDH + l_c8) * 2u,
                           kbase + DEMB + (size_t)r * D3 + l_c8);
            }
            CP_COMMIT();
        }

        float o[16][4];
        #pragma unroll
        for (int ni = 0; ni < 16; ni++)
            #pragma unroll
            for (int q = 0; q < 4; q++) o[ni][q] = 0.0f;
        float mrow0 = NEGINF, mrow1 = NEGINF, lrow0 = 0.0f, lrow1 = 0.0f;

        for (int jt = 0; jt <= qt; jt++) {
            const int p = jt & 1;
            const uint32_t Kcur = p ? Ku1 : Ku0;
            const uint32_t Vcur = p ? Vu1 : Vu0;

            CP_WAIT(0);            // all pending (current tile data) arrived
            __syncthreads();       // visible to all; prior-buffer reads ordered

            // ---- prefetch next K/V into alternate buffers (after barrier) ----
            if (jt < qt) {
                const uint32_t Knxt = p ? Ku0 : Ku1;
                const uint32_t Vnxt = p ? Vu0 : Vu1;
                const __half* kbn = qkv + (size_t)(b * SEQL + (jt + 1) * 128) * D3 + DEMB + h * DHEAD;
                #pragma unroll
                for (int i = 0; i < 8; i++) {
                    int r = l_r + i * 16;
                    cp_async16(Knxt + (uint32_t)(r * LDH + l_c8) * 2u, kbn + (size_t)r * D3 + l_c8);
                }
                CP_COMMIT();
                #pragma unroll
                for (int i = 0; i < 8; i++) {
                    int r = l_r + i * 16;
                    cp_async16(Vnxt + (uint32_t)(r * LDH + l_c8) * 2u,
                               kbn + DEMB + (size_t)r * D3 + l_c8);
                }
                CP_COMMIT();
            }

            // ---- S = Q @ K^T ----
            float s[16][4];
            #pragma unroll
            for (int ni = 0; ni < 16; ni++)
                #pragma unroll
                for (int q = 0; q < 4; q++) s[ni][q] = 0.0f;

            #pragma unroll
            for (int ks = 0; ks < 8; ks++) {
                const int kb = ks * 16;
                uint32_t af[4];
                ldsm_x4(af, Qu + (uint32_t)(((wid * 16 + a_row) * LDH) + kb + a_koff) * 2u);
                #pragma unroll
                for (int nj = 0; nj < 8; nj++) {
                    uint32_t r4[4];
                    ldsm_x4(r4, Kcur + (uint32_t)(((nj * 16 + kb_row) * LDH) + kb + kb_koff) * 2u);
                    mma_f16(s[2 * nj],     af, r4);
                    mma_f16(s[2 * nj + 1], af, r4 + 2);
                }
            }

            // ---- causal mask on diagonal tile ----
            if (jt == qt) {
                const int r0 = wid * 16 + g;
                #pragma unroll
                for (int ni = 0; ni < 16; ni++) {
                    const int c = ni * 8 + 2 * t;
                    if (c     > r0)     s[ni][0] = NEGINF;
                    if (c + 1 > r0)     s[ni][1] = NEGINF;
                    if (c     > r0 + 8) s[ni][2] = NEGINF;
                    if (c + 1 > r0 + 8) s[ni][3] = NEGINF;
                }
            }

            // ---- row max (warp-local) ----
            float m0 = NEGINF, m1 = NEGINF;
            #pragma unroll
            for (int ni = 0; ni < 16; ni++) {
                m0 = fmaxf(m0, fmaxf(s[ni][0], s[ni][1]));
                m1 = fmaxf(m1, fmaxf(s[ni][2], s[ni][3]));
            }
            #pragma unroll
            for (int off = 1; off <= 2; off <<= 1) {
                m0 = fmaxf(m0, __shfl_xor_sync(0xffffffffu, m0, off));
                m1 = fmaxf(m1, __shfl_xor_sync(0xffffffffu, m1, off));
            }
            const float mn0 = fmaxf(mrow0, m0);
            const float mn1 = fmaxf(mrow1, m1);
            const float fsc0 = ex2(mrow0 - mn0);
            const float fsc1 = ex2(mrow1 - mn1);
            mrow0 = mn0; mrow1 = mn1;

            // ---- exp + row sums ----
            float rs0 = 0.0f, rs1 = 0.0f;
            #pragma unroll
            for (int ni = 0; ni < 16; ni++) {
                s[ni][0] = ex2(s[ni][0] - mn0);
                s[ni][1] = ex2(s[ni][1] - mn0);
                s[ni][2] = ex2(s[ni][2] - mn1);
                s[ni][3] = ex2(s[ni][3] - mn1);
                rs0 += s[ni][0] + s[ni][1];
                rs1 += s[ni][2] + s[ni][3];
            }
            #pragma unroll
            for (int off = 1; off <= 2; off <<= 1) {
                rs0 += __shfl_xor_sync(0xffffffffu, rs0, off);
                rs1 += __shfl_xor_sync(0xffffffffu, rs1, off);
            }
            lrow0 = lrow0 * fsc0 + rs0;
            lrow1 = lrow1 * fsc1 + rs1;

            // ---- O rescale ----
            #pragma unroll
            for (int ni = 0; ni < 16; ni++) {
                o[ni][0] *= fsc0; o[ni][1] *= fsc0;
                o[ni][2] *= fsc1; o[ni][3] *= fsc1;
            }

            // ---- O += P @ V : P direct from registers ----
            #pragma unroll
            for (int ks = 0; ks < 8; ks++) {
                const int kb = ks * 16;
                uint32_t af[4];
                af[0] = packh2(s[2 * ks][0],     s[2 * ks][1]);
                af[1] = packh2(s[2 * ks][2],     s[2 * ks][3]);
                af[2] = packh2(s[2 * ks + 1][0], s[2 * ks + 1][1]);
                af[3] = packh2(s[2 * ks + 1][2], s[2 * ks + 1][3]);
                #pragma unroll
                for (int nj = 0; nj < 8; nj++) {
                    uint32_t r4[4];
                    ldsm_x4_trans(r4,
                        Vcur + (uint32_t)(((kb + vb_row) * LDH) + nj * 16 + vb_coff) * 2u);
                    mma_f16(o[2 * nj],     af, r4);
                    mma_f16(o[2 * nj + 1], af, r4 + 2);
                }
            }
            // no trailing barrier: next iter's barrier orders buffer reuse
        }

        // ---- epilogue: O /= l, fp16 out ----
        const size_t orow = (size_t)(b * SEQL + qt * 128) + wid * 16 + g;
        const float i0 = 1.0f / lrow0;
        const float i1 = 1.0f / lrow1;
        #pragma unroll
        for (int ni = 0; ni < 16; ni++) {
            const int cc = h * DHEAD + ni * 8 + 2 * t;
            *(__half2*)(attn_out + orow * DEMB + cc) =
                __floats2half2_rn(o[ni][0] * i0, o[ni][1] * i0);
            *(__half2*)(attn_out + (orow + 8) * DEMB + cc) =
                __floats2half2_rn(o[ni][2] * i1, o[ni][3] * i1);
        }
        __syncthreads();           // all reads done before next half's loads
    }
}

// ================================================================
// Launcher
// ================================================================
extern "C" void kernel_launch(void* const* d_in, const int* in_sizes, int n_in,
                              void* d_out, int out_size)
{
    (void)in_sizes; (void)n_in; (void)out_size;
    const float* x     = (const float*)d_in[0];
    const float* w_in  = (const float*)d_in[1];
    const float* b_in  = (const float*)d_in[2];
    const float* w_out = (const float*)d_in[3];
    const float* b_out = (const float*)d_in[4];
    float* out = (float*)d_out;

    void *qkv_p, *attn_p, *xh_p, *wT1_p, *wT2_p;
    cudaGetSymbolAddress(&qkv_p,  g_qkv);
    cudaGetSymbolAddress(&attn_p, g_attn);
    cudaGetSymbolAddress(&xh_p,   g_xh);
    cudaGetSymbolAddress(&wT1_p,  g_wT1);
    cudaGetSymbolAddress(&wT2_p,  g_wT2);

    cudaFuncSetAttribute(flash_f16_kernel,
                         cudaFuncAttributeMaxDynamicSharedMemorySize, FLASH_SMEM);
    cudaFuncSetAttribute(f16_mma_gemm_kernel,
                         cudaFuncAttributeMaxDynamicSharedMemorySize, GEMM_SMEM);

    // prep: wT1 = h(w_in^T), wT2 = h(w_out^T), xh = h(x)
    transpose_h_kernel<<<dim3(D3 / 32, DEMB / 32), dim3(32, 8)>>>(w_in, (__half*)wT1_p, DEMB, D3);
    transpose_h_kernel<<<dim3(DEMB / 32, DEMB / 32), dim3(32, 8)>>>(w_out, (__half*)wT2_p, DEMB, DEMB);
    conv_h_kernel<<<(NTOK * DEMB / 4 + 255) / 256, 256>>>(x, (__half*)xh_p, NTOK * DEMB / 4);

    // 1) qkv = x @ w_in + b_in  (fp16 out; Q cols pre-scaled by QSC)
    f16_mma_gemm_kernel<<<dim3(NTOK / 128, D3 / 128), 256, GEMM_SMEM>>>(
        (const __half*)xh_p, (const __half*)wT1_p, b_in,
        (__half*)qkv_p, nullptr, NTOK, D3, DEMB, DEMB);

    // 2) causal flash attention (paired q-tiles, single-barrier loop)
    flash_f16_kernel<<<dim3(NQT / 2, NHEADS, BATCH), 256, FLASH_SMEM>>>(
        (const __half*)qkv_p, (__half*)attn_p);

    // 3) out = attn @ w_out + b_out  (fp32 out)
    f16_mma_gemm_kernel<<<dim3(NTOK / 128, DEMB / 128), 256, GEMM_SMEM>>>(
        (const __half*)attn_p, (const __half*)wT2_p, b_out,
        nullptr, out, NTOK, DEMB, DEMB, 0);
}

// round 17
// speedup vs baseline: 1.1419x; 1.0033x over previous
#include <cuda_runtime.h>
#include <cuda_fp16.h>
#include <math.h>
#include <stdint.h>

#define BATCH   2
#define SEQL    2048
#define DEMB    2048
#define NHEADS  16
#define DHEAD   128
#define NTOK    (BATCH * SEQL)       // 4096
#define D3      (3 * DEMB)           // 6144
#define NQT     (SEQL / 128)         // 16 q-tiles

// combined score scale: log2(e)/sqrt(128), folded into Q at GEMM1 epilogue
#define QSC 0.1275174446f
#define NEGINF __int_as_float(0xff800000)

// -------- scratch (__device__ globals; no allocs allowed) --------
__device__ __half g_qkv [(size_t)NTOK * D3];     // 48 MB (fp16, Q pre-scaled)
__device__ __half g_attn[(size_t)NTOK * DEMB];   // 16 MB
__device__ __half g_xh  [(size_t)NTOK * DEMB];   // 16 MB (fp16 x)
__device__ __half g_wT1 [(size_t)D3   * DEMB];   // 24 MB (w_in^T fp16)
__device__ __half g_wT2 [(size_t)DEMB * DEMB];   //  8 MB (w_out^T fp16)

// ---------------- helpers ----------------
__device__ __forceinline__ uint32_t smem_u32(const void* p) {
    uint32_t a;
    asm("{ .reg .u64 t; cvta.to.shared.u64 t, %1; cvt.u32.u64 %0, t; }" : "=r"(a) : "l"(p));
    return a;
}
__device__ __forceinline__ float ex2(float x) {
    float y; asm("ex2.approx.f32 %0, %1;" : "=f"(y) : "f"(x)); return y;
}
__device__ __forceinline__ void cp_async16(uint32_t dst, const void* src) {
    asm volatile("cp.async.cg.shared.global [%0], [%1], 16;" :: "r"(dst), "l"(src) : "memory");
}
#define CP_COMMIT() asm volatile("cp.async.commit_group;" ::: "memory")
#define CP_WAIT(n)  asm volatile("cp.async.wait_group %0;" :: "n"(n) : "memory")

__device__ __forceinline__ void mma_f16(float* c, const uint32_t* a, const uint32_t* b) {
    asm volatile(
        "mma.sync.aligned.m16n8k16.row.col.f32.f16.f16.f32 "
        "{%0,%1,%2,%3}, {%4,%5,%6,%7}, {%8,%9}, {%0,%1,%2,%3};"
        : "+f"(c[0]), "+f"(c[1]), "+f"(c[2]), "+f"(c[3])
        : "r"(a[0]), "r"(a[1]), "r"(a[2]), "r"(a[3]), "r"(b[0]), "r"(b[1]));
}
__device__ __forceinline__ void ldsm_x4(uint32_t* r, uint32_t addr) {
    asm volatile("ldmatrix.sync.aligned.m8n8.x4.shared.b16 {%0,%1,%2,%3}, [%4];"
        : "=r"(r[0]), "=r"(r[1]), "=r"(r[2]), "=r"(r[3]) : "r"(addr));
}
__device__ __forceinline__ void ldsm_x4_trans(uint32_t* r, uint32_t addr) {
    asm volatile("ldmatrix.sync.aligned.m8n8.x4.trans.shared.b16 {%0,%1,%2,%3}, [%4];"
        : "=r"(r[0]), "=r"(r[1]), "=r"(r[2]), "=r"(r[3]) : "r"(addr));
}
__device__ __forceinline__ uint32_t packh2(float lo, float hi) {
    __half2 h = __floats2half2_rn(lo, hi);
    return *(uint32_t*)&h;
}

// ================================================================
// Prep kernels: fp16-convert x, transpose+convert weights to [N][K]
// ================================================================
__global__ void transpose_h_kernel(const float* __restrict__ src, __half* __restrict__ dst,
                                   int R, int C) {
    __shared__ float tile[32][33];
    int bx = blockIdx.x * 32, by = blockIdx.y * 32;
    int x = bx + threadIdx.x;
    for (int i = threadIdx.y; i < 32; i += 8)
        tile[i][threadIdx.x] = src[(size_t)(by + i) * C + x];
    __syncthreads();
    int ox = by + threadIdx.x;
    for (int i = threadIdx.y; i < 32; i += 8)
        dst[(size_t)(bx + i) * R + ox] = __float2half_rn(tile[threadIdx.x][i]);
}

__global__ void conv_h_kernel(const float* __restrict__ src, __half* __restrict__ dst, int n4) {
    int i = blockIdx.x * blockDim.x + threadIdx.x;
    if (i < n4) {
        float4 v = ((const float4*)src)[i];
        ((__half2*)dst)[2 * i]     = __floats2half2_rn(v.x, v.y);
        ((__half2*)dst)[2 * i + 1] = __floats2half2_rn(v.z, v.w);
    }
}

// ================================================================
// fp16 mma GEMM (R13 version): CTA 128x128, warp 64x32, K-chunk 64,
// 3-stage cp.async, paired-B ldmatrix, 2 CTAs/SM.
// ================================================================
#define LDT 72
#define STG_H (256 * LDT)
#define STG_B (STG_H * 2)
#define GEMM_SMEM (3 * STG_B)                            // 110592 B

__global__ __launch_bounds__(256, 2) void f16_mma_gemm_kernel(
    const __half* __restrict__ A, const __half* __restrict__ Bt,
    const float* __restrict__ bias, __half* __restrict__ Ch, float* __restrict__ Cf,
    int M, int N, int K, int qcols)
{
    extern __shared__ __half smh[];
    const int tid  = threadIdx.x;
    const int lane = tid & 31;
    const int wid  = tid >> 5;
    const int wm = wid >> 2;
    const int wn = wid & 3;
    const int g = lane >> 2, t = lane & 3;
    const int bm = blockIdx.x * 128;
    const int bn = blockIdx.y * 128;
    const int nchunks = K >> 6;

    const int a_row  = (lane & 7) + ((lane >> 3) & 1) * 8;
    const int a_koff = (lane >> 4) * 8;
    const int pb_row  = (lane & 7) + ((lane >> 4) & 1) * 8;
    const int pb_koff = ((lane >> 3) & 1) * 8;

    const uint32_t smb = smem_u32(smh);

    float acc[4][4][4];
    #pragma unroll
    for (int mi = 0; mi < 4; mi++)
        #pragma unroll
        for (int ni = 0; ni < 4; ni++)
            #pragma unroll
            for (int q = 0; q < 4; q++) acc[mi][ni][q] = 0.0f;

    const int l_r  = tid >> 3;
    const int l_c8 = (tid & 7) * 8;

    auto load_stage = [&](int c, uint32_t baseA) {
        const int kb = c << 6;
        const uint32_t baseB = baseA + 128u * LDT * 2u;
        #pragma unroll
        for (int i = 0; i < 8; i++) {
            int r = l_r + i * 32;
            if (r < 128)
                cp_async16(baseA + (uint32_t)(r * LDT + l_c8) * 2u,
                           A + (size_t)(bm + r) * K + kb + l_c8);
            else
                cp_async16(baseB + (uint32_t)((r - 128) * LDT + l_c8) * 2u,
                           Bt + (size_t)(bn + r - 128) * K + kb + l_c8);
        }
        CP_COMMIT();
    };

    uint32_t sb0 = smb, sb1 = smb + STG_B, sb2 = smb + 2u * STG_B;

    load_stage(0, sb0);
    if (nchunks > 1) load_stage(1, sb1);

    for (int c = 0; c < nchunks; c++) {
        if (c + 1 < nchunks) { CP_WAIT(1); } else { CP_WAIT(0); }
        __syncthreads();

        if (c + 2 < nchunks) load_stage(c + 2, sb2);

        const uint32_t sAu = sb0;
        const uint32_t sBu = sb0 + 128u * LDT * 2u;
        #pragma unroll
        for (int ks = 0; ks < 4; ks++) {
            const int kb = ks * 16;
            uint32_t af[4][4], bf[2][4];
            #pragma unroll
            for (int mi = 0; mi < 4; mi++)
                ldsm_x4(af[mi],
                    sAu + (uint32_t)(((wm * 64 + mi * 16 + a_row) * LDT) + kb + a_koff) * 2u);
            #pragma unroll
            for (int nj = 0; nj < 2; nj++)
                ldsm_x4(bf[nj],
                    sBu + (uint32_t)(((wn * 32 + nj * 16 + pb_row) * LDT) + kb + pb_koff) * 2u);
            #pragma unroll
            for (int mi = 0; mi < 4; mi++)
                #pragma unroll
                for (int ni = 0; ni < 4; ni++)
                    mma_f16(acc[mi][ni], af[mi], bf[ni >> 1] + (ni & 1) * 2);
        }
        uint32_t tmp = sb0; sb0 = sb1; sb1 = sb2; sb2 = tmp;
    }
    __syncthreads();

    #pragma unroll
    for (int mi = 0; mi < 4; mi++) {
        const int r0 = bm + wm * 64 + mi * 16 + g;
        #pragma unroll
        for (int ni = 0; ni < 4; ni++) {
            const int n = bn + wn * 32 + ni * 8 + t * 2;
            const float sc = (n < qcols) ? QSC : 1.0f;
            float2 bv = *(const float2*)(bias + n);
            float v0 = (acc[mi][ni][0] + bv.x) * sc;
            float v1 = (acc[mi][ni][1] + bv.y) * sc;
            float v2 = (acc[mi][ni][2] + bv.x) * sc;
            float v3 = (acc[mi][ni][3] + bv.y) * sc;
            if (Ch) {
                *(__half2*)(Ch + (size_t)r0 * N + n)       = __floats2half2_rn(v0, v1);
                *(__half2*)(Ch + (size_t)(r0 + 8) * N + n) = __floats2half2_rn(v2, v3);
            } else {
                *(float2*)(Cf + (size_t)r0 * N + n)       = make_float2(v0, v1);
                *(float2*)(Cf + (size_t)(r0 + 8) * N + n) = make_float2(v2, v3);
            }
        }
    }
}

// ================================================================
// Flash attention, FA2-style, paired q-tiles, single barrier/iter,
// Q FRAGMENTS REGISTER-HOISTED (loaded once per q-tile; isolates the
// R12 experiment — all indices static, fully unrolled, no predicates).
// ================================================================
#define LDH 136
#define FL_TILE (128 * LDH * 2)                         // 34816 B
#define FLB_Q   0
#define FLB_K0  (FL_TILE)
#define FLB_K1  (2 * FL_TILE)
#define FLB_V0  (3 * FL_TILE)
#define FLB_V1  (4 * FL_TILE)
#define FLASH_SMEM (5 * FL_TILE)                        // 174080 B

__global__ __launch_bounds__(256, 1) void flash_f16_kernel(
    const __half* __restrict__ qkv, __half* __restrict__ attn_out)
{
    extern __shared__ char smc[];

    const int h   = blockIdx.y;
    const int b   = blockIdx.z;
    const int tid  = threadIdx.x;
    const int lane = tid & 31;
    const int wid  = tid >> 5;
    const int g = lane >> 2, t = lane & 3;

    const int a_row  = (lane & 7) + ((lane >> 3) & 1) * 8;
    const int a_koff = (lane >> 4) * 8;
    const int kb_row  = (lane & 7) + ((lane >> 4) & 1) * 8;
    const int kb_koff = ((lane >> 3) & 1) * 8;
    const int vb_row  = (lane & 7) + ((lane >> 3) & 1) * 8;
    const int vb_coff = ((lane >> 4) & 1) * 8;

    const uint32_t smb = smem_u32(smc);
    const uint32_t Qu  = smb + FLB_Q;
    const uint32_t Ku0 = smb + FLB_K0, Ku1 = smb + FLB_K1;
    const uint32_t Vu0 = smb + FLB_V0, Vu1 = smb + FLB_V1;

    const int l_r  = tid >> 4;               // 0..15
    const int l_c8 = (tid & 15) * 8;

    #pragma unroll
    for (int half = 0; half < 2; half++) {
        // heavy tile first, then its light complement: uniform 17 iters/CTA
        const int qt = half == 0 ? (NQT - 1 - (int)blockIdx.x) : (int)blockIdx.x;

        // ---- Q, K0, V0 loads (3 groups) ----
        const __half* qbase = qkv + (size_t)(b * SEQL + qt * 128) * D3 + h * DHEAD;
        #pragma unroll
        for (int i = 0; i < 8; i++) {
            int r = l_r + i * 16;
            cp_async16(Qu + (uint32_t)(r * LDH + l_c8) * 2u, qbase + (size_t)r * D3 + l_c8);
        }
        CP_COMMIT();
        {
            const __half* kbase = qkv + (size_t)(b * SEQL) * D3 + DEMB + h * DHEAD;
            #pragma unroll
            for (int i = 0; i < 8; i++) {
                int r = l_r + i * 16;
                cp_async16(Ku0 + (uint32_t)(r * LDH + l_c8) * 2u, kbase + (size_t)r * D3 + l_c8);
            }
            CP_COMMIT();
            #pragma unroll
            for (int i = 0; i < 8; i++) {
                int r = l_r + i * 16;
                cp_async16(Vu0 + (uint32_t)(r * LDH + l_c8) * 2u,
                           kbase + DEMB + (size_t)r * D3 + l_c8);
            }
            CP_COMMIT();
        }

        float o[16][4];
        #pragma unroll
        for (int ni = 0; ni < 16; ni++)
            #pragma unroll
            for (int q = 0; q < 4; q++) o[ni][q] = 0.0f;
        float mrow0 = NEGINF, mrow1 = NEGINF, lrow0 = 0.0f, lrow1 = 0.0f;

        uint32_t aq[8][4];       // register-hoisted Q fragments (full dh)

        for (int jt = 0; jt <= qt; jt++) {
            const int p = jt & 1;
            const uint32_t Kcur = p ? Ku1 : Ku0;
            const uint32_t Vcur = p ? Vu1 : Vu0;

            CP_WAIT(0);            // all pending (current tile data) arrived
            __syncthreads();       // visible to all; prior-buffer reads ordered

            // ---- hoist Q fragments once per q-tile ----
            if (jt == 0) {
                #pragma unroll
                for (int ks = 0; ks < 8; ks++)
                    ldsm_x4(aq[ks],
                        Qu + (uint32_t)(((wid * 16 + a_row) * LDH) + ks * 16 + a_koff) * 2u);
            }

            // ---- prefetch next K/V into alternate buffers (after barrier) ----
            if (jt < qt) {
                const uint32_t Knxt = p ? Ku0 : Ku1;
                const uint32_t Vnxt = p ? Vu0 : Vu1;
                const __half* kbn = qkv + (size_t)(b * SEQL + (jt + 1) * 128) * D3 + DEMB + h * DHEAD;
                #pragma unroll
                for (int i = 0; i < 8; i++) {
                    int r = l_r + i * 16;
                    cp_async16(Knxt + (uint32_t)(r * LDH + l_c8) * 2u, kbn + (size_t)r * D3 + l_c8);
                }
                CP_COMMIT();
                #pragma unroll
                for (int i = 0; i < 8; i++) {
                    int r = l_r + i * 16;
                    cp_async16(Vnxt + (uint32_t)(r * LDH + l_c8) * 2u,
                               kbn + DEMB + (size_t)r * D3 + l_c8);
                }
                CP_COMMIT();
            }

            // ---- S = Q @ K^T ----
            float s[16][4];
            #pragma unroll
            for (int ni = 0; ni < 16; ni++)
                #pragma unroll
                for (int q = 0; q < 4; q++) s[ni][q] = 0.0f;

            #pragma unroll
            for (int ks = 0; ks < 8; ks++) {
                const int kb = ks * 16;
                #pragma unroll
                for (int nj = 0; nj < 8; nj++) {
                    uint32_t r4[4];
                    ldsm_x4(r4, Kcur + (uint32_t)(((nj * 16 + kb_row) * LDH) + kb + kb_koff) * 2u);
                    mma_f16(s[2 * nj],     aq[ks], r4);
                    mma_f16(s[2 * nj + 1], aq[ks], r4 + 2);
                }
            }

            // ---- causal mask on diagonal tile ----
            if (jt == qt) {
                const int r0 = wid * 16 + g;
                #pragma unroll
                for (int ni = 0; ni < 16; ni++) {
                    const int c = ni * 8 + 2 * t;
                    if (c     > r0)     s[ni][0] = NEGINF;
                    if (c + 1 > r0)     s[ni][1] = NEGINF;
                    if (c     > r0 + 8) s[ni][2] = NEGINF;
                    if (c + 1 > r0 + 8) s[ni][3] = NEGINF;
                }
            }

            // ---- row max (warp-local) ----
            float m0 = NEGINF, m1 = NEGINF;
            #pragma unroll
            for (int ni = 0; ni < 16; ni++) {
                m0 = fmaxf(m0, fmaxf(s[ni][0], s[ni][1]));
                m1 = fmaxf(m1, fmaxf(s[ni][2], s[ni][3]));
            }
            #pragma unroll
            for (int off = 1; off <= 2; off <<= 1) {
                m0 = fmaxf(m0, __shfl_xor_sync(0xffffffffu, m0, off));
                m1 = fmaxf(m1, __shfl_xor_sync(0xffffffffu, m1, off));
            }
            const float mn0 = fmaxf(mrow0, m0);
            const float mn1 = fmaxf(mrow1, m1);
            const float fsc0 = ex2(mrow0 - mn0);
            const float fsc1 = ex2(mrow1 - mn1);
            mrow0 = mn0; mrow1 = mn1;

            // ---- exp + row sums ----
            float rs0 = 0.0f, rs1 = 0.0f;
            #pragma unroll
            for (int ni = 0; ni < 16; ni++) {
                s[ni][0] = ex2(s[ni][0] - mn0);
                s[ni][1] = ex2(s[ni][1] - mn0);
                s[ni][2] = ex2(s[ni][2] - mn1);
                s[ni][3] = ex2(s[ni][3] - mn1);
                rs0 += s[ni][0] + s[ni][1];
                rs1 += s[ni][2] + s[ni][3];
            }
            #pragma unroll
            for (int off = 1; off <= 2; off <<= 1) {
                rs0 += __shfl_xor_sync(0xffffffffu, rs0, off);
                rs1 += __shfl_xor_sync(0xffffffffu, rs1, off);
            }
            lrow0 = lrow0 * fsc0 + rs0;
            lrow1 = lrow1 * fsc1 + rs1;

            // ---- O rescale ----
            #pragma unroll
            for (int ni = 0; ni < 16; ni++) {
                o[ni][0] *= fsc0; o[ni][1] *= fsc0;
                o[ni][2] *= fsc1; o[ni][3] *= fsc1;
            }

            // ---- O += P @ V : P direct from registers ----
            #pragma unroll
            for (int ks = 0; ks < 8; ks++) {
                const int kb = ks * 16;
                uint32_t af[4];
                af[0] = packh2(s[2 * ks][0],     s[2 * ks][1]);
                af[1] = packh2(s[2 * ks][2],     s[2 * ks][3]);
                af[2] = packh2(s[2 * ks + 1][0], s[2 * ks + 1][1]);
                af[3] = packh2(s[2 * ks + 1][2], s[2 * ks + 1][3]);
                #pragma unroll
                for (int nj = 0; nj < 8; nj++) {
                    uint32_t r4[4];
                    ldsm_x4_trans(r4,
                        Vcur + (uint32_t)(((kb + vb_row) * LDH) + nj * 16 + vb_coff) * 2u);
                    mma_f16(o[2 * nj],     af, r4);
                    mma_f16(o[2 * nj + 1], af, r4 + 2);
                }
            }
            // no trailing barrier: next iter's barrier orders buffer reuse
        }

        // ---- epilogue: O /= l, fp16 out ----
        const size_t orow = (size_t)(b * SEQL + qt * 128) + wid * 16 + g;
        const float i0 = 1.0f / lrow0;
        const float i1 = 1.0f / lrow1;
        #pragma unroll
        for (int ni = 0; ni < 16; ni++) {
            const int cc = h * DHEAD + ni * 8 + 2 * t;
            *(__half2*)(attn_out + orow * DEMB + cc) =
                __floats2half2_rn(o[ni][0] * i0, o[ni][1] * i0);
            *(__half2*)(attn_out + (orow + 8) * DEMB + cc) =
                __floats2half2_rn(o[ni][2] * i1, o[ni][3] * i1);
        }
        __syncthreads();           // all reads done before next half's loads
    }
}

// ================================================================
// Launcher
// ================================================================
extern "C" void kernel_launch(void* const* d_in, const int* in_sizes, int n_in,
                              void* d_out, int out_size)
{
    (void)in_sizes; (void)n_in; (void)out_size;
    const float* x     = (const float*)d_in[0];
    const float* w_in  = (const float*)d_in[1];
    const float* b_in  = (const float*)d_in[2];
    const float* w_out = (const float*)d_in[3];
    const float* b_out = (const float*)d_in[4];
    float* out = (float*)d_out;

    void *qkv_p, *attn_p, *xh_p, *wT1_p, *wT2_p;
    cudaGetSymbolAddress(&qkv_p,  g_qkv);
    cudaGetSymbolAddress(&attn_p, g_attn);
    cudaGetSymbolAddress(&xh_p,   g_xh);
    cudaGetSymbolAddress(&wT1_p,  g_wT1);
    cudaGetSymbolAddress(&wT2_p,  g_wT2);

    cudaFuncSetAttribute(flash_f16_kernel,
                         cudaFuncAttributeMaxDynamicSharedMemorySize, FLASH_SMEM);
    cudaFuncSetAttribute(f16_mma_gemm_kernel,
                         cudaFuncAttributeMaxDynamicSharedMemorySize, GEMM_SMEM);

    // prep: wT1 = h(w_in^T), wT2 = h(w_out^T), xh = h(x)
    transpose_h_kernel<<<dim3(D3 / 32, DEMB / 32), dim3(32, 8)>>>(w_in, (__half*)wT1_p, DEMB, D3);
    transpose_h_kernel<<<dim3(DEMB / 32, DEMB / 32), dim3(32, 8)>>>(w_out, (__half*)wT2_p, DEMB, DEMB);
    conv_h_kernel<<<(NTOK * DEMB / 4 + 255) / 256, 256>>>(x, (__half*)xh_p, NTOK * DEMB / 4);

    // 1) qkv = x @ w_in + b_in  (fp16 out; Q cols pre-scaled by QSC)
    f16_mma_gemm_kernel<<<dim3(NTOK / 128, D3 / 128), 256, GEMM_SMEM>>>(
        (const __half*)xh_p, (const __half*)wT1_p, b_in,
        (__half*)qkv_p, nullptr, NTOK, D3, DEMB, DEMB);

    // 2) causal flash attention (paired q-tiles, hoisted Q frags)
    flash_f16_kernel<<<dim3(NQT / 2, NHEADS, BATCH), 256, FLASH_SMEM>>>(
        (const __half*)qkv_p, (__half*)attn_p);

    // 3) out = attn @ w_out + b_out  (fp32 out)
    f16_mma_gemm_kernel<<<dim3(NTOK / 128, DEMB / 128), 256, GEMM_SMEM>>>(
        (const __half*)attn_p, (const __half*)wT2_p, b_out,
        nullptr, out, NTOK, DEMB, DEMB, 0);
}